// round 1
// baseline (speedup 1.0000x reference)
#include <cuda_runtime.h>
#include <cuda_bf16.h>

// Problem constants (fixed by setup_inputs)
#define T_TOK  8192
#define DIM    4096
#define KS     4
#define NSLOT  128
#define TOPK   1024
#define MAXL   4096   // worst case: all TOPK*KS writes land on one slot

// Scratch (no allocations allowed -> __device__ globals)
__device__ float g_imp[T_TOK];
__device__ int   g_slot_cnt[NSLOT];
__device__ int   g_slot_list[NSLOT * MAXL];

// ---------------------------------------------------------------------------
// Kernel 1: per-token importance.  One block per token, 256 threads.
// Reads the whole hidden_states (128MB) -> HBM-bound.
// ---------------------------------------------------------------------------
__global__ void __launch_bounds__(256)
importance_kernel(const float* __restrict__ h,
                  const float* __restrict__ aw,
                  const float* __restrict__ W,
                  const float* __restrict__ b)
{
    int t = blockIdx.x;
    const float4* hr = (const float4*)(h + (size_t)t * DIM);
    const float4* wr = (const float4*)W;

    float ssq = 0.f, dot = 0.f;
#pragma unroll
    for (int k = 0; k < 4; k++) {
        int i = threadIdx.x + k * 256;           // coalesced float4
        float4 hv = hr[i];
        float4 wv = wr[i];
        ssq += hv.x*hv.x + hv.y*hv.y + hv.z*hv.z + hv.w*hv.w;
        dot += hv.x*wv.x + hv.y*wv.y + hv.z*wv.z + hv.w*wv.w;
    }
    // warp reduce
#pragma unroll
    for (int off = 16; off > 0; off >>= 1) {
        ssq += __shfl_down_sync(0xffffffffu, ssq, off);
        dot += __shfl_down_sync(0xffffffffu, dot, off);
    }
    __shared__ float s_ssq[8], s_dot[8];
    int lane = threadIdx.x & 31, wid = threadIdx.x >> 5;
    if (lane == 0) { s_ssq[wid] = ssq; s_dot[wid] = dot; }
    __syncthreads();
    if (threadIdx.x == 0) {
        float S = 0.f, Dd = 0.f;
#pragma unroll
        for (int i = 0; i < 8; i++) { S += s_ssq[i]; Dd += s_dot[i]; }
        float mag = sqrtf(S);
        float ent = 0.f;
#pragma unroll
        for (int j = 0; j < KS; j++) {
            float a = aw[t * KS + j];
            ent -= a * logf(a + 1e-8f);
        }
        float sur = ent * (1.0f / 1.3862943611198906f);   // / log(4)
        float learned = 1.0f / (1.0f + expf(-(Dd + b[0])));
        g_imp[t] = mag * (1.0f + sur) + learned;
    }
}

// ---------------------------------------------------------------------------
// Kernel 2: exact top-1024 radix select (1 block, 1024 threads) + per-slot
// token lists via shared atomics.  Index-ordered tie handling.
// ---------------------------------------------------------------------------
__global__ void __launch_bounds__(1024)
select_kernel(const int* __restrict__ slot_idx)
{
    __shared__ unsigned s_keys[T_TOK];    // 32 KB
    __shared__ int      s_hist[256];
    __shared__ int      s_cnt[NSLOT];
    __shared__ unsigned s_prefix, s_pmask;
    __shared__ int      s_k;
    __shared__ int      s_wsum[32];

    int tid = threadIdx.x;
    if (tid < NSLOT) s_cnt[tid] = 0;

    // load keys (monotone float->uint transform)
#pragma unroll
    for (int j = 0; j < 8; j++) {
        int t = tid + j * 1024;
        unsigned u = __float_as_uint(g_imp[t]);
        u = (u & 0x80000000u) ? ~u : (u | 0x80000000u);
        s_keys[t] = u;
    }
    if (tid == 0) { s_prefix = 0u; s_pmask = 0u; s_k = TOPK; }
    __syncthreads();

    // 4-pass MSB->LSB byte radix select for the 1024th-largest key
    for (int shift = 24; shift >= 0; shift -= 8) {
        if (tid < 256) s_hist[tid] = 0;
        __syncthreads();
        unsigned pmask = s_pmask, prefix = s_prefix;
#pragma unroll
        for (int j = 0; j < 8; j++) {
            unsigned u = s_keys[tid + j * 1024];
            if ((u & pmask) == prefix) atomicAdd(&s_hist[(u >> shift) & 255], 1);
        }
        __syncthreads();
        if (tid == 0) {
            int k = s_k, cum = 0, bsel = 0;
            for (int bkt = 255; bkt >= 0; bkt--) {
                int c = s_hist[bkt];
                if (cum + c >= k) { bsel = bkt; s_k = k - cum; break; }
                cum += c;
            }
            s_prefix = prefix | ((unsigned)bsel << shift);
            s_pmask  = pmask | (0xFFu << shift);
        }
        __syncthreads();
    }
    unsigned thr = s_prefix;
    int need_eq  = s_k;         // #keys == thr to take (in token-index order)

    // block exclusive scan of per-thread equal-to-threshold counts
    int base = tid * 8;
    int loc_eq = 0;
#pragma unroll
    for (int j = 0; j < 8; j++) loc_eq += (s_keys[base + j] == thr);

    int lane = tid & 31, wid = tid >> 5;
    int inc = loc_eq;
#pragma unroll
    for (int off = 1; off < 32; off <<= 1) {
        int n = __shfl_up_sync(0xffffffffu, inc, off);
        if (lane >= off) inc += n;
    }
    if (lane == 31) s_wsum[wid] = inc;
    __syncthreads();
    if (wid == 0) {
        int v = s_wsum[lane];
        int iv = v;
#pragma unroll
        for (int off = 1; off < 32; off <<= 1) {
            int n = __shfl_up_sync(0xffffffffu, iv, off);
            if (lane >= off) iv += n;
        }
        s_wsum[lane] = iv - v;    // exclusive warp-prefix
    }
    __syncthreads();
    int run = s_wsum[wid] + (inc - loc_eq);   // exclusive prefix of equals

    // scatter selected tokens into per-slot lists
#pragma unroll
    for (int j = 0; j < 8; j++) {
        int t = base + j;
        unsigned u = s_keys[t];
        bool sel = (u > thr);
        if (u == thr) { sel = (run < need_eq); run++; }
        if (sel) {
            int4 sl = ((const int4*)slot_idx)[t];
            int ss[4] = { sl.x, sl.y, sl.z, sl.w };
#pragma unroll
            for (int q = 0; q < KS; q++) {
                int slot = ss[q];
                int pos = atomicAdd(&s_cnt[slot], 1);
                g_slot_list[slot * MAXL + pos] = t;
            }
        }
    }
    __syncthreads();
    if (tid < NSLOT) g_slot_cnt[tid] = s_cnt[tid];
}

// ---------------------------------------------------------------------------
// Kernel 3: gather-aggregate per slot + EMA write.
// grid = (4 chunks of 1024 floats, 128 slots), block = 256 threads (float4 each).
// ---------------------------------------------------------------------------
__global__ void __launch_bounds__(256)
aggregate_kernel(const float* __restrict__ h,
                 const float* __restrict__ mem,
                 float* __restrict__ out)
{
    int slot = blockIdx.y;
    int d = blockIdx.x * 1024 + threadIdx.x * 4;
    int cnt = g_slot_cnt[slot];
    const int* lst = &g_slot_list[slot * MAXL];

    float4 acc = make_float4(0.f, 0.f, 0.f, 0.f);
    int i = 0;
    for (; i + 1 < cnt; i += 2) {
        int t0 = lst[i], t1 = lst[i + 1];
        float4 a = *(const float4*)(h + (size_t)t0 * DIM + d);
        float4 c = *(const float4*)(h + (size_t)t1 * DIM + d);
        acc.x += a.x + c.x; acc.y += a.y + c.y;
        acc.z += a.z + c.z; acc.w += a.w + c.w;
    }
    if (i < cnt) {
        int t0 = lst[i];
        float4 a = *(const float4*)(h + (size_t)t0 * DIM + d);
        acc.x += a.x; acc.y += a.y; acc.z += a.z; acc.w += a.w;
    }

    float4 cur = *(const float4*)(mem + (size_t)slot * DIM + d);
    float4 o;
    if (cnt > 0) {
        float inv = 1.0f / (float)cnt;
        o.x = 0.1f * (acc.x * inv) + 0.9f * cur.x;
        o.y = 0.1f * (acc.y * inv) + 0.9f * cur.y;
        o.z = 0.1f * (acc.z * inv) + 0.9f * cur.z;
        o.w = 0.1f * (acc.w * inv) + 0.9f * cur.w;
    } else {
        o = cur;
    }
    *(float4*)(out + (size_t)slot * DIM + d) = o;
}

// ---------------------------------------------------------------------------
extern "C" void kernel_launch(void* const* d_in, const int* in_sizes, int n_in,
                              void* d_out, int out_size)
{
    const float* h   = (const float*)d_in[0];   // hidden_states [8192,4096]
    const float* aw  = (const float*)d_in[1];   // attention_weights [8192,4]
    const float* mem = (const float*)d_in[2];   // memory [1,128,4096]
    const float* W   = (const float*)d_in[3];   // W_imp [1,4096]
    const float* b   = (const float*)d_in[4];   // b_imp [1]
    const int*   si  = (const int*)d_in[5];     // slot_indices [8192,4]
    float* out = (float*)d_out;                 // [1,128,4096]

    importance_kernel<<<T_TOK, 256>>>(h, aw, W, b);
    select_kernel<<<1, 1024>>>(si);
    aggregate_kernel<<<dim3(4, NSLOT), 256>>>(h, mem, out);
}

// round 7
// speedup vs baseline: 1.0763x; 1.0763x over previous
#include <cuda_runtime.h>
#include <cuda_bf16.h>

// Problem constants (fixed by setup_inputs)
#define T_TOK  8192
#define DIM    4096
#define KS     4
#define NSLOT  128
#define TOPK   1024
#define MAXL   4096   // worst case: all TOPK*KS writes land on one slot

// Scratch (no allocations allowed -> __device__ globals)
__device__ float g_imp[T_TOK];
__device__ int   g_slot_cnt[NSLOT];
__device__ int   g_slot_list[NSLOT * MAXL];

// ---------------------------------------------------------------------------
// Kernel 1: per-token importance.  One WARP per token (no block reduce, no
// syncthreads).  Each lane reads float4s strided by 32 -> fully coalesced,
// unroll 8 for deep MLP.  Warp-shuffle reduce, lane 0 does the scalar tail.
// ---------------------------------------------------------------------------
__global__ void __launch_bounds__(256)
importance_kernel(const float* __restrict__ h,
                  const float* __restrict__ aw,
                  const float* __restrict__ W,
                  const float* __restrict__ b)
{
    int warp = (blockIdx.x * 256 + threadIdx.x) >> 5;   // token id 0..8191
    int lane = threadIdx.x & 31;

    const float4* __restrict__ hr = (const float4*)(h + (size_t)warp * DIM);
    const float4* __restrict__ wr = (const float4*)W;

    float ssq = 0.f, dot = 0.f;
#pragma unroll 8
    for (int k = 0; k < 32; k++) {
        int i = lane + (k << 5);
        float4 hv = hr[i];
        float4 wv = wr[i];
        ssq = fmaf(hv.x, hv.x, ssq); ssq = fmaf(hv.y, hv.y, ssq);
        ssq = fmaf(hv.z, hv.z, ssq); ssq = fmaf(hv.w, hv.w, ssq);
        dot = fmaf(hv.x, wv.x, dot); dot = fmaf(hv.y, wv.y, dot);
        dot = fmaf(hv.z, wv.z, dot); dot = fmaf(hv.w, wv.w, dot);
    }
#pragma unroll
    for (int off = 16; off > 0; off >>= 1) {
        ssq += __shfl_down_sync(0xffffffffu, ssq, off);
        dot += __shfl_down_sync(0xffffffffu, dot, off);
    }
    if (lane == 0) {
        float4 a4 = ((const float4*)aw)[warp];     // KS = 4 weights
        float ent = -(a4.x * logf(a4.x + 1e-8f) + a4.y * logf(a4.y + 1e-8f) +
                      a4.z * logf(a4.z + 1e-8f) + a4.w * logf(a4.w + 1e-8f));
        float sur = ent * (1.0f / 1.3862943611198906f);    // / log(4)
        float learned = 1.0f / (1.0f + expf(-(dot + b[0])));
        g_imp[warp] = sqrtf(ssq) * (1.0f + sur) + learned;
    }
}

// ---------------------------------------------------------------------------
// Kernel 2: exact top-1024 radix select (1 block, 1024 threads) + per-slot
// token lists via shared atomics.  Index-ordered tie handling.
// ---------------------------------------------------------------------------
__global__ void __launch_bounds__(1024)
select_kernel(const int* __restrict__ slot_idx)
{
    __shared__ unsigned s_keys[T_TOK];    // 32 KB
    __shared__ int      s_hist[256];
    __shared__ int      s_cnt[NSLOT];
    __shared__ unsigned s_prefix, s_pmask;
    __shared__ int      s_k;
    __shared__ int      s_wsum[32];

    int tid = threadIdx.x;
    if (tid < NSLOT) s_cnt[tid] = 0;

    // load keys (monotone float->uint transform)
#pragma unroll
    for (int j = 0; j < 8; j++) {
        int t = tid + j * 1024;
        unsigned u = __float_as_uint(g_imp[t]);
        u = (u & 0x80000000u) ? ~u : (u | 0x80000000u);
        s_keys[t] = u;
    }
    if (tid == 0) { s_prefix = 0u; s_pmask = 0u; s_k = TOPK; }
    __syncthreads();

    // 4-pass MSB->LSB byte radix select for the 1024th-largest key
    for (int shift = 24; shift >= 0; shift -= 8) {
        if (tid < 256) s_hist[tid] = 0;
        __syncthreads();
        unsigned pmask = s_pmask, prefix = s_prefix;
#pragma unroll
        for (int j = 0; j < 8; j++) {
            unsigned u = s_keys[tid + j * 1024];
            if ((u & pmask) == prefix) atomicAdd(&s_hist[(u >> shift) & 255], 1);
        }
        __syncthreads();
        if (tid == 0) {
            int k = s_k, cum = 0, bsel = 0;
            for (int bkt = 255; bkt >= 0; bkt--) {
                int c = s_hist[bkt];
                if (cum + c >= k) { bsel = bkt; s_k = k - cum; break; }
                cum += c;
            }
            s_prefix = prefix | ((unsigned)bsel << shift);
            s_pmask  = pmask | (0xFFu << shift);
        }
        __syncthreads();
    }
    unsigned thr = s_prefix;
    int need_eq  = s_k;         // #keys == thr to take (in token-index order)

    // block exclusive scan of per-thread equal-to-threshold counts
    int base = tid * 8;
    int loc_eq = 0;
#pragma unroll
    for (int j = 0; j < 8; j++) loc_eq += (s_keys[base + j] == thr);

    int lane = tid & 31, wid = tid >> 5;
    int inc = loc_eq;
#pragma unroll
    for (int off = 1; off < 32; off <<= 1) {
        int n = __shfl_up_sync(0xffffffffu, inc, off);
        if (lane >= off) inc += n;
    }
    if (lane == 31) s_wsum[wid] = inc;
    __syncthreads();
    if (wid == 0) {
        int v = s_wsum[lane];
        int iv = v;
#pragma unroll
        for (int off = 1; off < 32; off <<= 1) {
            int n = __shfl_up_sync(0xffffffffu, iv, off);
            if (lane >= off) iv += n;
        }
        s_wsum[lane] = iv - v;    // exclusive warp-prefix
    }
    __syncthreads();
    int run = s_wsum[wid] + (inc - loc_eq);   // exclusive prefix of equals

    // scatter selected tokens into per-slot lists
#pragma unroll
    for (int j = 0; j < 8; j++) {
        int t = base + j;
        unsigned u = s_keys[t];
        bool sel = (u > thr);
        if (u == thr) { sel = (run < need_eq); run++; }
        if (sel) {
            int4 sl = ((const int4*)slot_idx)[t];
            int ss[4] = { sl.x, sl.y, sl.z, sl.w };
#pragma unroll
            for (int q = 0; q < KS; q++) {
                int slot = ss[q];
                int pos = atomicAdd(&s_cnt[slot], 1);
                g_slot_list[slot * MAXL + pos] = t;
            }
        }
    }
    __syncthreads();
    if (tid < NSLOT) g_slot_cnt[tid] = s_cnt[tid];
}

// ---------------------------------------------------------------------------
// Kernel 3: gather-aggregate per slot + EMA write.
// grid = (8 chunks of 512 floats, 128 slots) = 1024 blocks, 128 threads.
// Token loop unrolled x4 with 2 independent accumulators -> 4 loads in flight
// per thread.
// ---------------------------------------------------------------------------
__global__ void __launch_bounds__(128)
aggregate_kernel(const float* __restrict__ h,
                 const float* __restrict__ mem,
                 float* __restrict__ out)
{
    int slot = blockIdx.y;
    int d = blockIdx.x * 512 + threadIdx.x * 4;
    int cnt = g_slot_cnt[slot];
    const int* __restrict__ lst = &g_slot_list[slot * MAXL];

    float4 acc0 = make_float4(0.f, 0.f, 0.f, 0.f);
    float4 acc1 = make_float4(0.f, 0.f, 0.f, 0.f);
    int i = 0;
    for (; i + 3 < cnt; i += 4) {
        int t0 = lst[i], t1 = lst[i + 1], t2 = lst[i + 2], t3 = lst[i + 3];
        float4 a = *(const float4*)(h + (size_t)t0 * DIM + d);
        float4 c = *(const float4*)(h + (size_t)t1 * DIM + d);
        float4 e = *(const float4*)(h + (size_t)t2 * DIM + d);
        float4 f = *(const float4*)(h + (size_t)t3 * DIM + d);
        acc0.x += a.x + c.x; acc0.y += a.y + c.y;
        acc0.z += a.z + c.z; acc0.w += a.w + c.w;
        acc1.x += e.x + f.x; acc1.y += e.y + f.y;
        acc1.z += e.z + f.z; acc1.w += e.w + f.w;
    }
    for (; i < cnt; i++) {
        int t0 = lst[i];
        float4 a = *(const float4*)(h + (size_t)t0 * DIM + d);
        acc0.x += a.x; acc0.y += a.y; acc0.z += a.z; acc0.w += a.w;
    }
    acc0.x += acc1.x; acc0.y += acc1.y; acc0.z += acc1.z; acc0.w += acc1.w;

    float4 cur = *(const float4*)(mem + (size_t)slot * DIM + d);
    float4 o;
    if (cnt > 0) {
        float inv = 1.0f / (float)cnt;
        o.x = fmaf(0.1f * inv, acc0.x, 0.9f * cur.x);
        o.y = fmaf(0.1f * inv, acc0.y, 0.9f * cur.y);
        o.z = fmaf(0.1f * inv, acc0.z, 0.9f * cur.z);
        o.w = fmaf(0.1f * inv, acc0.w, 0.9f * cur.w);
    } else {
        o = cur;
    }
    *(float4*)(out + (size_t)slot * DIM + d) = o;
}

// ---------------------------------------------------------------------------
extern "C" void kernel_launch(void* const* d_in, const int* in_sizes, int n_in,
                              void* d_out, int out_size)
{
    const float* h   = (const float*)d_in[0];   // hidden_states [8192,4096]
    const float* aw  = (const float*)d_in[1];   // attention_weights [8192,4]
    const float* mem = (const float*)d_in[2];   // memory [1,128,4096]
    const float* W   = (const float*)d_in[3];   // W_imp [1,4096]
    const float* b   = (const float*)d_in[4];   // b_imp [1]
    const int*   si  = (const int*)d_in[5];     // slot_indices [8192,4]
    float* out = (float*)d_out;                 // [1,128,4096]

    importance_kernel<<<T_TOK / 8, 256>>>(h, aw, W, b);   // 1 warp / token
    select_kernel<<<1, 1024>>>(si);
    aggregate_kernel<<<dim3(8, NSLOT), 128>>>(h, mem, out);
}

// round 9
// speedup vs baseline: 1.0983x; 1.0205x over previous
#include <cuda_runtime.h>
#include <cuda_bf16.h>

// Problem constants (fixed by setup_inputs)
#define T_TOK  8192
#define DIM    4096
#define KS     4
#define NSLOT  128
#define TOPK   1024
#define MAXL   4096   // worst case: all TOPK*KS writes land on one slot

// Scratch (no allocations allowed -> __device__ globals)
__device__ float g_imp[T_TOK];
__device__ int   g_slot_cnt[NSLOT];
__device__ int   g_slot_list[NSLOT * MAXL];

// ---------------------------------------------------------------------------
// Kernel 1: per-token importance.  One WARP per token.  W staged in shared
// memory once per block -> inner loop is 1 LDG.128 (stream) + 1 LDS.128.
// ---------------------------------------------------------------------------
__global__ void __launch_bounds__(256)
importance_kernel(const float* __restrict__ h,
                  const float* __restrict__ aw,
                  const float* __restrict__ W,
                  const float* __restrict__ b)
{
    __shared__ float4 s_W[DIM / 4];          // 16 KB

    // cooperative W load: 256 threads x 4 float4
#pragma unroll
    for (int j = 0; j < 4; j++)
        s_W[threadIdx.x + j * 256] = ((const float4*)W)[threadIdx.x + j * 256];
    __syncthreads();

    int warp = (blockIdx.x * 256 + threadIdx.x) >> 5;   // token id 0..8191
    int lane = threadIdx.x & 31;

    const float4* __restrict__ hr = (const float4*)(h + (size_t)warp * DIM);

    float ssq = 0.f, dot = 0.f;
#pragma unroll 8
    for (int k = 0; k < 32; k++) {
        int i = lane + (k << 5);
        float4 hv = hr[i];
        float4 wv = s_W[i];
        ssq = fmaf(hv.x, hv.x, ssq); ssq = fmaf(hv.y, hv.y, ssq);
        ssq = fmaf(hv.z, hv.z, ssq); ssq = fmaf(hv.w, hv.w, ssq);
        dot = fmaf(hv.x, wv.x, dot); dot = fmaf(hv.y, wv.y, dot);
        dot = fmaf(hv.z, wv.z, dot); dot = fmaf(hv.w, wv.w, dot);
    }
#pragma unroll
    for (int off = 16; off > 0; off >>= 1) {
        ssq += __shfl_down_sync(0xffffffffu, ssq, off);
        dot += __shfl_down_sync(0xffffffffu, dot, off);
    }
    if (lane == 0) {
        float4 a4 = ((const float4*)aw)[warp];     // KS = 4 weights
        float ent = -(a4.x * logf(a4.x + 1e-8f) + a4.y * logf(a4.y + 1e-8f) +
                      a4.z * logf(a4.z + 1e-8f) + a4.w * logf(a4.w + 1e-8f));
        float sur = ent * (1.0f / 1.3862943611198906f);    // / log(4)
        float learned = 1.0f / (1.0f + expf(-(dot + b[0])));
        g_imp[warp] = sqrtf(ssq) * (1.0f + sur) + learned;
    }
}

// ---------------------------------------------------------------------------
// Kernel 2: exact top-1024 radix select (1 block, 1024 threads) + per-slot
// token lists via shared atomics.  Bucket pick is now WARP-PARALLEL
// (8 buckets/lane + shuffle suffix-scan) instead of a serial 256-iteration
// single-thread loop with dependent LDS.
// ---------------------------------------------------------------------------
__global__ void __launch_bounds__(1024)
select_kernel(const int* __restrict__ slot_idx)
{
    __shared__ unsigned s_keys[T_TOK];    // 32 KB
    __shared__ int      s_hist[256];
    __shared__ int      s_cnt[NSLOT];
    __shared__ unsigned s_prefix, s_pmask;
    __shared__ int      s_k;
    __shared__ int      s_wsum[32];

    int tid = threadIdx.x;
    if (tid < NSLOT) s_cnt[tid] = 0;

    // load keys (monotone float->uint transform)
#pragma unroll
    for (int j = 0; j < 8; j++) {
        int t = tid + j * 1024;
        unsigned u = __float_as_uint(g_imp[t]);
        u = (u & 0x80000000u) ? ~u : (u | 0x80000000u);
        s_keys[t] = u;
    }
    if (tid == 0) { s_prefix = 0u; s_pmask = 0u; s_k = TOPK; }
    __syncthreads();

    // 4-pass MSB->LSB byte radix select for the 1024th-largest key
    for (int shift = 24; shift >= 0; shift -= 8) {
        if (tid < 256) s_hist[tid] = 0;
        __syncthreads();
        unsigned pmask = s_pmask, prefix = s_prefix;
#pragma unroll
        for (int j = 0; j < 8; j++) {
            unsigned u = s_keys[tid + j * 1024];
            if ((u & pmask) == prefix) atomicAdd(&s_hist[(u >> shift) & 255], 1);
        }
        __syncthreads();
        // warp 0: parallel suffix-scan over 256 buckets (8 per lane)
        if (tid < 32) {
            int k = s_k;
            int h8[8];
            int tot = 0;
#pragma unroll
            for (int j = 0; j < 8; j++) { h8[j] = s_hist[tid * 8 + j]; tot += h8[j]; }
            // inclusive suffix-scan of per-lane totals: suf = sum over lanes >= tid
            int suf = tot;
#pragma unroll
            for (int off = 1; off < 32; off <<= 1) {
                int n = __shfl_down_sync(0xffffffffu, suf, off);
                if (tid + off < 32) suf += n;
            }
            int tail = suf - tot;   // sum of buckets in lanes > tid
            // per-bucket suffix sums within this lane (bucket b = tid*8+j)
            int sfx[8];
            int s = tail;
#pragma unroll
            for (int j = 7; j >= 0; j--) { s += h8[j]; sfx[j] = s; }
            // unique bucket with suffix(b) >= k > suffix(b) - hist[b]
#pragma unroll
            for (int j = 0; j < 8; j++) {
                int above = sfx[j] - h8[j];
                if (sfx[j] >= k && above < k) {
                    s_prefix = prefix | ((unsigned)(tid * 8 + j) << shift);
                    s_pmask  = pmask | (0xFFu << shift);
                    s_k      = k - above;
                }
            }
        }
        __syncthreads();
    }
    unsigned thr = s_prefix;
    int need_eq  = s_k;         // #keys == thr to take (in token-index order)

    // block exclusive scan of per-thread equal-to-threshold counts
    int base = tid * 8;
    int loc_eq = 0;
#pragma unroll
    for (int j = 0; j < 8; j++) loc_eq += (s_keys[base + j] == thr);

    int lane = tid & 31, wid = tid >> 5;
    int inc = loc_eq;
#pragma unroll
    for (int off = 1; off < 32; off <<= 1) {
        int n = __shfl_up_sync(0xffffffffu, inc, off);
        if (lane >= off) inc += n;
    }
    if (lane == 31) s_wsum[wid] = inc;
    __syncthreads();
    if (wid == 0) {
        int v = s_wsum[lane];
        int iv = v;
#pragma unroll
        for (int off = 1; off < 32; off <<= 1) {
            int n = __shfl_up_sync(0xffffffffu, iv, off);
            if (lane >= off) iv += n;
        }
        s_wsum[lane] = iv - v;    // exclusive warp-prefix
    }
    __syncthreads();
    int run = s_wsum[wid] + (inc - loc_eq);   // exclusive prefix of equals

    // scatter selected tokens into per-slot lists
#pragma unroll
    for (int j = 0; j < 8; j++) {
        int t = base + j;
        unsigned u = s_keys[t];
        bool sel = (u > thr);
        if (u == thr) { sel = (run < need_eq); run++; }
        if (sel) {
            int4 sl = ((const int4*)slot_idx)[t];
            int ss[4] = { sl.x, sl.y, sl.z, sl.w };
#pragma unroll
            for (int q = 0; q < KS; q++) {
                int slot = ss[q];
                int pos = atomicAdd(&s_cnt[slot], 1);
                g_slot_list[slot * MAXL + pos] = t;
            }
        }
    }
    __syncthreads();
    if (tid < NSLOT) g_slot_cnt[tid] = s_cnt[tid];
}

// ---------------------------------------------------------------------------
// Kernel 3: gather-aggregate per slot + EMA write.
// grid = (8 chunks of 512 floats, 128 slots) = 1024 blocks, 128 threads.
// Token loop unrolled x8 with 4 independent accumulators -> 8 loads in
// flight per thread.
// ---------------------------------------------------------------------------
__global__ void __launch_bounds__(128)
aggregate_kernel(const float* __restrict__ h,
                 const float* __restrict__ mem,
                 float* __restrict__ out)
{
    int slot = blockIdx.y;
    int d = blockIdx.x * 512 + threadIdx.x * 4;
    int cnt = g_slot_cnt[slot];
    const int* __restrict__ lst = &g_slot_list[slot * MAXL];

    float4 acc0 = make_float4(0.f, 0.f, 0.f, 0.f);
    float4 acc1 = make_float4(0.f, 0.f, 0.f, 0.f);
    float4 acc2 = make_float4(0.f, 0.f, 0.f, 0.f);
    float4 acc3 = make_float4(0.f, 0.f, 0.f, 0.f);
    int i = 0;
    for (; i + 7 < cnt; i += 8) {
        int t0 = lst[i],     t1 = lst[i + 1], t2 = lst[i + 2], t3 = lst[i + 3];
        int t4 = lst[i + 4], t5 = lst[i + 5], t6 = lst[i + 6], t7 = lst[i + 7];
        float4 v0 = *(const float4*)(h + (size_t)t0 * DIM + d);
        float4 v1 = *(const float4*)(h + (size_t)t1 * DIM + d);
        float4 v2 = *(const float4*)(h + (size_t)t2 * DIM + d);
        float4 v3 = *(const float4*)(h + (size_t)t3 * DIM + d);
        float4 v4 = *(const float4*)(h + (size_t)t4 * DIM + d);
        float4 v5 = *(const float4*)(h + (size_t)t5 * DIM + d);
        float4 v6 = *(const float4*)(h + (size_t)t6 * DIM + d);
        float4 v7 = *(const float4*)(h + (size_t)t7 * DIM + d);
        acc0.x += v0.x + v1.x; acc0.y += v0.y + v1.y;
        acc0.z += v0.z + v1.z; acc0.w += v0.w + v1.w;
        acc1.x += v2.x + v3.x; acc1.y += v2.y + v3.y;
        acc1.z += v2.z + v3.z; acc1.w += v2.w + v3.w;
        acc2.x += v4.x + v5.x; acc2.y += v4.y + v5.y;
        acc2.z += v4.z + v5.z; acc2.w += v4.w + v5.w;
        acc3.x += v6.x + v7.x; acc3.y += v6.y + v7.y;
        acc3.z += v6.z + v7.z; acc3.w += v6.w + v7.w;
    }
    for (; i < cnt; i++) {
        int t0 = lst[i];
        float4 a = *(const float4*)(h + (size_t)t0 * DIM + d);
        acc0.x += a.x; acc0.y += a.y; acc0.z += a.z; acc0.w += a.w;
    }
    acc0.x += acc1.x + acc2.x + acc3.x;
    acc0.y += acc1.y + acc2.y + acc3.y;
    acc0.z += acc1.z + acc2.z + acc3.z;
    acc0.w += acc1.w + acc2.w + acc3.w;

    float4 cur = *(const float4*)(mem + (size_t)slot * DIM + d);
    float4 o;
    if (cnt > 0) {
        float inv = 1.0f / (float)cnt;
        o.x = fmaf(0.1f * inv, acc0.x, 0.9f * cur.x);
        o.y = fmaf(0.1f * inv, acc0.y, 0.9f * cur.y);
        o.z = fmaf(0.1f * inv, acc0.z, 0.9f * cur.z);
        o.w = fmaf(0.1f * inv, acc0.w, 0.9f * cur.w);
    } else {
        o = cur;
    }
    *(float4*)(out + (size_t)slot * DIM + d) = o;
}

// ---------------------------------------------------------------------------
extern "C" void kernel_launch(void* const* d_in, const int* in_sizes, int n_in,
                              void* d_out, int out_size)
{
    const float* h   = (const float*)d_in[0];   // hidden_states [8192,4096]
    const float* aw  = (const float*)d_in[1];   // attention_weights [8192,4]
    const float* mem = (const float*)d_in[2];   // memory [1,128,4096]
    const float* W   = (const float*)d_in[3];   // W_imp [1,4096]
    const float* b   = (const float*)d_in[4];   // b_imp [1]
    const int*   si  = (const int*)d_in[5];     // slot_indices [8192,4]
    float* out = (float*)d_out;                 // [1,128,4096]

    importance_kernel<<<T_TOK / 8, 256>>>(h, aw, W, b);   // 1 warp / token
    select_kernel<<<1, 1024>>>(si);
    aggregate_kernel<<<dim3(8, NSLOT), 128>>>(h, mem, out);
}